// round 6
// baseline (speedup 1.0000x reference)
#include <cuda_runtime.h>
#include <math.h>

#define N_ROWS   16384
#define ACTIONS  64
#define EMB      32
#define DELTA    16
#define EPSF     1e-5f
#define NB1      128
#define ROWS_PER_B1 (N_ROWS / NB1)   // 128

// Scratch (no allocation allowed in kernel_launch): BN partial sums.
__device__ float g_psum[NB1][ACTIONS];
__device__ float g_psq [NB1][ACTIONS];

// ---------------------------------------------------------------------------
// Kernel 1: per-block partial sum / sumsq per action column.
// float4 loads, explicit 8-deep load batch (MLP=8, 128 B in flight/thread).
// Deterministic: fixed-order reductions, no atomics.
// ---------------------------------------------------------------------------
__global__ __launch_bounds__(256) void bn_partial(const float* __restrict__ x)
{
    const int tid = threadIdx.x;
    const int c4  = tid & 15;
    const int r   = tid >> 4;
    const int b   = blockIdx.x;

    const float4* px = reinterpret_cast<const float4*>(x)
                     + (size_t)(b * ROWS_PER_B1 + r) * (ACTIONS / 4) + c4;

    float4 v[8];
#pragma unroll
    for (int k = 0; k < 8; k++)
        v[k] = __ldg(px + (size_t)k * 16 * (ACTIONS / 4));   // +16 rows each

    float4 s = {0.f, 0.f, 0.f, 0.f};
    float4 q = {0.f, 0.f, 0.f, 0.f};
#pragma unroll
    for (int k = 0; k < 8; k++) {
        s.x += v[k].x; q.x += v[k].x * v[k].x;
        s.y += v[k].y; q.y += v[k].y * v[k].y;
        s.z += v[k].z; q.z += v[k].z * v[k].z;
        s.w += v[k].w; q.w += v[k].w * v[k].w;
    }

    __shared__ float4 ss[16][16];
    __shared__ float4 sq[16][16];
    ss[r][c4] = s;
    sq[r][c4] = q;
    __syncthreads();

    if (tid < ACTIONS) {
        const int c = tid;
        const int cc = c >> 2, ce = c & 3;
        float ts = 0.f, tq = 0.f;
#pragma unroll
        for (int r2 = 0; r2 < 16; r2++) {
            ts += reinterpret_cast<const float*>(&ss[r2][cc])[ce];
            tq += reinterpret_cast<const float*>(&sq[r2][cc])[ce];
        }
        g_psum[b][c] = ts;
        g_psq [b][c] = tq;
    }
}

// ---------------------------------------------------------------------------
// Kernel 2 (fused): per-block BN finalize prologue + spline main loop.
//  - Prologue: every block tree-reduces the 128 partials for its action.
//    Fixed pairing => bit-identical scale/shift in every block (deterministic).
//    Kills the separate bn_finalize launch (+its ~3us overhead).
//  - Main: 8 warps x 4 pairs/warp x 8 iterations = 256 rows per block.
//    grid (64 row-tiles, 64 actions) = 4096 fat blocks (was 32768 tiny ones)
//    -> ~4 waves instead of ~27, x-loads batched by full unroll.
//  - tanh/index once per pair (lanes 0..3), broadcast via shfl.
//  - per-action table slice = 33 rows * 128B = 4.2 KB -> L1-resident gathers.
//  - xh = xl + 1 always => bh row = bl row + 64; wl = 1 - wh exactly.
//  - __stcs streaming stores keep the 134 MB write stream out of L2.
// ---------------------------------------------------------------------------
__global__ __launch_bounds__(256) void spline_fused(const float* __restrict__ x,
                                                    const float* __restrict__ emb,
                                                    const float* __restrict__ wgt,
                                                    const float* __restrict__ bias,
                                                    float* __restrict__ out)
{
    const int tid = threadIdx.x;
    const int a   = blockIdx.y;

    // ---- BN finalize prologue (deterministic tree reduce of 128 partials) ----
    __shared__ float rs[NB1];
    __shared__ float rq[NB1];
    __shared__ float s_sc, s_sh;

    if (tid < NB1) {
        rs[tid] = g_psum[tid][a];
        rq[tid] = g_psq [tid][a];
    }
    __syncthreads();
#pragma unroll
    for (int off = NB1 / 2; off > 0; off >>= 1) {
        if (tid < off) {
            rs[tid] += rs[tid + off];
            rq[tid] += rq[tid + off];
        }
        __syncthreads();
    }
    if (tid == 0) {
        const float inv_n = 1.0f / (float)N_ROWS;
        float mean = rs[0] * inv_n;
        float var  = fmaf(-mean, mean, rq[0] * inv_n);   // E[x^2] - mean^2
        float sc   = wgt[a] * rsqrtf(var + EPSF);
        s_sc = sc;
        s_sh = fmaf(-mean, sc, bias[a]);
    }
    __syncthreads();

    const float sc = s_sc;
    const float sh = s_sh;

    // ---- main spline loop ----
    const int lane  = tid & 31;
    const int wid   = tid >> 5;          // warp 0..7
    const int lane8 = lane & 7;          // float4 group within EMB
    const int g     = lane >> 3;         // pair within warp (0..3)
    const int row0  = blockIdx.x * 256 + wid * 4;

    const float4* emb4 = reinterpret_cast<const float4*>(emb);
    float4*       out4 = reinterpret_cast<float4*>(out);

#pragma unroll
    for (int it = 0; it < 8; it++) {
        const int rb = row0 + it * 32;

        float wh_v = 0.f;
        int   li_v = 0;
        if (lane < 4) {
            const float xv = __ldg(x + (size_t)(rb + lane) * ACTIONS + a);
            float t = tanhf(fmaf(xv, sc, sh));
            t = fminf(fmaxf(t, -1.0f + 1e-5f), 1.0f - 1e-5f);
            const float f   = t * (float)DELTA;      // exact (power-of-2 scale)
            const float xlf = floorf(f);
            wh_v = f - xlf;                           // = DELTA*(t - xl), exact
            li_v = (((int)xlf) + DELTA) * ACTIONS + a;
        }
        const float wh = __shfl_sync(0xffffffffu, wh_v, g);
        const int   li = __shfl_sync(0xffffffffu, li_v, g);
        const float wl = 1.0f - wh;                   // = DELTA*(xh - t)

        const float4* bl4 = emb4 + (size_t)li * (EMB / 4) + lane8;
        const float4 bl = __ldg(bl4);
        const float4 bh = __ldg(bl4 + (size_t)ACTIONS * (EMB / 4)); // row + 64

        float4 h;
        h.x = bh.x * wh + bl.x * wl;
        h.y = bh.y * wh + bl.y * wl;
        h.z = bh.z * wh + bl.z * wl;
        h.w = bh.w * wh + bl.w * wl;

        __stcs(out4 + (size_t)((rb + g) * ACTIONS + a) * (EMB / 4) + lane8, h);
    }
}

// ---------------------------------------------------------------------------
// Launch: x, bn_weight, bn_bias, emb_table  ->  out [n, ACTIONS, EMB] fp32
// ---------------------------------------------------------------------------
extern "C" void kernel_launch(void* const* d_in, const int* in_sizes, int n_in,
                              void* d_out, int out_size)
{
    const float* x    = (const float*)d_in[0];
    const float* wgt  = (const float*)d_in[1];
    const float* bias = (const float*)d_in[2];
    const float* emb  = (const float*)d_in[3];
    float* out        = (float*)d_out;

    bn_partial<<<NB1, 256>>>(x);

    dim3 grid(N_ROWS / 256, ACTIONS);   // (64, 64)
    spline_fused<<<grid, 256>>>(x, emb, wgt, bias, out);
}